// round 8
// baseline (speedup 1.0000x reference)
#include <cuda_runtime.h>

// EMA scan: s_t = (1-ALPHA)*x_t + ALPHA*s_{t-1}
// x: (T=1024, C=32*1024) fp32, state: (C,), out: (T, C) [+ final_state (C,)]
//
// Exact time-parallel decomposition, persistent-grid version.
//   block = 512 threads; per tile it covers 16 channels x full T.
//   lane -> (sub = lane/16, ch = lane%16); chunk = warpId*2 + sub (32 chunks of 32)
// Persistent loop over channel tiles: phase-3 STGs are fire-and-forget, so the
// next tile's load burst issues immediately behind them -> continuous mixed
// read/write stream, no wave-transition bubbles (grid = 2 x #SMs).

#define ALPHA_F 0.9f
#define NCHUNK 32
#define LCHUNK 32          // T = 1024
#define CH_BLK 16          // channels per tile
#define NUM_SMS 152        // GB300

// Compile-time alpha powers (folded under #pragma unroll)
__host__ __device__ __forceinline__ constexpr float apow(int n) {
    float p = 1.0f;
    for (int i = 0; i < n; i++) p *= ALPHA_F;
    return p;
}

__global__ __launch_bounds__(512, 2)
void ema_scan_par(const float* __restrict__ x,
                  const float* __restrict__ state,
                  float* __restrict__ out,
                  float* __restrict__ final_state,
                  int C, int num_tiles) {
    __shared__ float sp[NCHUNK][CH_BLK + 1];   // padded: conflict-free both ways

    const int tid  = threadIdx.x;
    const int wid  = tid >> 5;
    const int lane = tid & 31;
    const int sub  = lane >> 4;
    const int ch   = lane & 15;
    const int chunk = wid * 2 + sub;

    const float a = ALPHA_F;
    const float b = 1.0f - ALPHA_F;

    for (int tile = blockIdx.x; tile < num_tiles; tile += gridDim.x) {
        const int c = tile * CH_BLK + ch;

        // Prefetch the state warp 'wid' needs in phase 2; hides under load burst.
        float s0_pref = state[tile * CH_BLK + wid];

        // ---- Phase 1: loads (MLP=32) + zero-init local scan ----
        const float* __restrict__ xp = x + chunk * LCHUNK * C + c;
        float v[LCHUNK];
        #pragma unroll
        for (int i = 0; i < LCHUNK; i++) v[i] = __ldcs(xp + i * C);

        float s = 0.0f;
        #pragma unroll
        for (int i = 0; i < LCHUNK; i++) { s = v[i] * b + s * a; v[i] = s; }

        sp[chunk][ch] = s;
        __syncthreads();

        // ---- Phase 2: warp 'wid' scans 32 chunk maps of channel 'wid' ----
        {
            float p = sp[lane][wid];

            float Acc = apow(LCHUNK), Bcc = p;   // inclusive affine scan
            #pragma unroll
            for (int d = 1; d < NCHUNK; d <<= 1) {
                float Au = __shfl_up_sync(0xffffffffu, Acc, d);
                float Bu = __shfl_up_sync(0xffffffffu, Bcc, d);
                if (lane >= d) { Bcc = Acc * Bu + Bcc; Acc = Acc * Au; }
            }

            float sout = Acc * s0_pref + Bcc;            // state after chunk 'lane'
            float sin_ = __shfl_up_sync(0xffffffffu, sout, 1);
            if (lane == 0) sin_ = s0_pref;               // exclusive: incoming state

            sp[lane][wid] = sin_;
        }
        __syncthreads();

        // ---- Phase 3: fix up with compile-time alpha powers, streaming stores ----
        {
            float sin_ = sp[chunk][ch];
            float* __restrict__ op = out + chunk * LCHUNK * C + c;
            float olast = 0.0f;
            #pragma unroll
            for (int i = 0; i < LCHUNK; i++) {
                float o = v[i] + apow(i + 1) * sin_;     // independent FFMAs
                __stcs(op + i * C, o);
                olast = o;
            }
            if (final_state && chunk == NCHUNK - 1) final_state[c] = olast;
        }
        __syncthreads();   // protect sp[] before next tile overwrites it
    }
}

// Fallback: one thread per channel (any T, any C)
__global__ void ema_scan_fallback(const float* __restrict__ x,
                                  const float* __restrict__ state,
                                  float* __restrict__ out,
                                  float* __restrict__ final_state,
                                  int C, int T) {
    int c = blockIdx.x * blockDim.x + threadIdx.x;
    if (c >= C) return;
    const float a = ALPHA_F, b = 1.0f - ALPHA_F;
    float s = state[c];
    for (int t = 0; t < T; t++) {
        s = x[(size_t)t * C + c] * b + s * a;
        out[(size_t)t * C + c] = s;
    }
    if (final_state) final_state[c] = s;
}

extern "C" void kernel_launch(void* const* d_in, const int* in_sizes, int n_in,
                              void* d_out, int out_size) {
    const float* x     = (const float*)d_in[0];
    const float* state = (const float*)d_in[1];
    float* out = (float*)d_out;

    int x_elems = in_sizes[0];         // T * C
    int C = in_sizes[1];               // 32 * 1024
    int T = x_elems / C;               // 1024

    float* final_state = (out_size > x_elems) ? (out + x_elems) : nullptr;

    if (T == NCHUNK * LCHUNK && (C % CH_BLK) == 0) {
        int num_tiles = C / CH_BLK;
        int grid = 2 * NUM_SMS;
        if (grid > num_tiles) grid = num_tiles;
        ema_scan_par<<<grid, 512>>>(x, state, out, final_state, C, num_tiles);
    } else {
        int threads = 256;
        int blocks = (C + threads - 1) / threads;
        ema_scan_fallback<<<blocks, threads>>>(x, state, out, final_state, C, T);
    }
}